// round 2
// baseline (speedup 1.0000x reference)
#include <cuda_runtime.h>
#include <cuda_fp16.h>
#include <math.h>
#include <stdint.h>

// Problem dims (fixed by the dataset)
#define MDIM  8192   // 4 * 2048 rows of q
#define NBANK 8192   // memory bank rows
#define KDIM  1024   // feature dim
#define ODIM  1024   // out features
#define G1_GRIDN 64  // NBANK / 128

// ---------------- scratch (static device globals; no allocs) ----------------
__device__ __half g_qh [(size_t)MDIM  * KDIM ];          // q in fp16
__device__ __half g_kh [(size_t)NBANK * KDIM ];          // k in fp16
__device__ __half g_vhT[(size_t)ODIM  * NBANK];          // v transposed: [o][n]
__device__ float  g_S  [(size_t)MDIM  * NBANK];          // scores fp32 (268 MB)
__device__ __half g_G  [(size_t)MDIM  * NBANK];          // gated fp16  (134 MB)
__device__ float  g_partials[(size_t)MDIM * G1_GRIDN];   // per-(row, ntile) sumsq
__device__ float  g_invnorm [MDIM];

// ---------------- PTX helpers ----------------
__device__ __forceinline__ void cp_async16(void* smem, const void* gmem) {
    unsigned s = (unsigned)__cvta_generic_to_shared(smem);
    asm volatile("cp.async.cg.shared.global [%0], [%1], 16;\n" :: "r"(s), "l"(gmem));
}
__device__ __forceinline__ void cp_commit() { asm volatile("cp.async.commit_group;\n"); }
__device__ __forceinline__ void cp_wait1()  { asm volatile("cp.async.wait_group 1;\n"); }

__device__ __forceinline__ void ldsm4(uint32_t& r0, uint32_t& r1, uint32_t& r2, uint32_t& r3,
                                      const __half* p) {
    unsigned s = (unsigned)__cvta_generic_to_shared(p);
    asm volatile("ldmatrix.sync.aligned.m8n8.x4.shared.b16 {%0,%1,%2,%3}, [%4];\n"
                 : "=r"(r0), "=r"(r1), "=r"(r2), "=r"(r3) : "r"(s));
}
__device__ __forceinline__ void mma16816(float c[4], uint32_t a0, uint32_t a1, uint32_t a2,
                                         uint32_t a3, uint32_t b0, uint32_t b1) {
    asm volatile("mma.sync.aligned.m16n8k16.row.col.f32.f16.f16.f32 "
                 "{%0,%1,%2,%3}, {%4,%5,%6,%7}, {%8,%9}, {%0,%1,%2,%3};\n"
                 : "+f"(c[0]), "+f"(c[1]), "+f"(c[2]), "+f"(c[3])
                 : "r"(a0), "r"(a1), "r"(a2), "r"(a3), "r"(b0), "r"(b1));
}

// ---------------- kernel 0a: fp32 -> fp16 copy (vectorized) ----------------
__global__ void f2h_kernel(const float4* __restrict__ src, uint2* __restrict__ dst, int n4) {
    int i = blockIdx.x * blockDim.x + threadIdx.x;
    if (i >= n4) return;
    float4 v = src[i];
    __half2 h0 = __floats2half2_rn(v.x, v.y);
    __half2 h1 = __floats2half2_rn(v.z, v.w);
    uint2 o;
    o.x = *reinterpret_cast<unsigned*>(&h0);
    o.y = *reinterpret_cast<unsigned*>(&h1);
    dst[i] = o;
}

// ---------------- kernel 0b: v [NBANK][ODIM] -> fp16 vT [ODIM][NBANK] ----------------
__global__ void transpose_f2h_kernel(const float* __restrict__ v, __half* __restrict__ vt) {
    __shared__ float tile[32][33];
    int bx = blockIdx.x * 32;  // out-feature base
    int by = blockIdx.y * 32;  // bank base
    int tx = threadIdx.x, ty = threadIdx.y;  // block (32, 8)
#pragma unroll
    for (int j = 0; j < 32; j += 8)
        tile[ty + j][tx] = v[(size_t)(by + ty + j) * ODIM + bx + tx];
    __syncthreads();
#pragma unroll
    for (int j = 0; j < 32; j += 8)
        vt[(size_t)(bx + ty + j) * NBANK + by + tx] = __float2half(tile[tx][ty + j]);
}

// ---------------- GEMM NT: C[M,N] = A[M,K] * B[N,K]^T, fp16 in, fp32 accum/out -------
// Block 128x128x32, 256 threads, warps 2(M) x 4(N), warp tile 64x32.
// SUMSQ: additionally emit per-(row, blockN) sum of squares (deterministic, no atomics).
template <bool SUMSQ>
__global__ void __launch_bounds__(256) gemm_nt_kernel(
    const __half* __restrict__ A, const __half* __restrict__ B, float* __restrict__ C,
    int K, int N, float* __restrict__ partials, int gridN) {
    constexpr int BM = 128, BN = 128, BK = 32, LDS = BK + 8;  // 80B row: ldmatrix conflict-free
    __shared__ __half As[2][BM * LDS];
    __shared__ __half Bs[2][BN * LDS];
    __shared__ float red[4][BM];

    const int tid = threadIdx.x, lane = tid & 31, wid = tid >> 5;
    const int wm = wid >> 2, wn = wid & 3;
    const int bm = blockIdx.y * BM, bn = blockIdx.x * BN;

    float c[4][4][4];
#pragma unroll
    for (int a = 0; a < 4; a++)
#pragma unroll
        for (int b = 0; b < 4; b++)
#pragma unroll
            for (int i = 0; i < 4; i++) c[a][b][i] = 0.f;

    // ---- async tile loader: 512 16B chunks per operand, 2 per thread ----
    auto load_tile = [&](int buf, int k0) {
#pragma unroll
        for (int i = 0; i < 2; i++) {
            int ch = tid + i * 256;
            int r = ch >> 2, cc = (ch & 3) * 8;  // 8 halves = 16B per chunk
            cp_async16(&As[buf][r * LDS + cc], A + (size_t)(bm + r) * K + k0 + cc);
            cp_async16(&Bs[buf][r * LDS + cc], B + (size_t)(bn + r) * K + k0 + cc);
        }
    };

    const int NT = K / BK;
    load_tile(0, 0);
    cp_commit();

    for (int kt = 0; kt < NT; ++kt) {
        const int buf = kt & 1;
        if (kt + 1 < NT) load_tile(buf ^ 1, (kt + 1) * BK);
        cp_commit();
        cp_wait1();
        __syncthreads();

#pragma unroll
        for (int ks = 0; ks < 2; ++ks) {  // two k16 steps inside BK=32
            uint32_t a[4][4], b[4][2];
            const int rr = lane & 15, cc = (lane >> 4) * 8 + ks * 16;
#pragma unroll
            for (int mt = 0; mt < 4; ++mt)
                ldsm4(a[mt][0], a[mt][1], a[mt][2], a[mt][3],
                      &As[buf][(wm * 64 + mt * 16 + rr) * LDS + cc]);
#pragma unroll
            for (int bt = 0; bt < 2; ++bt) {  // one x4 covers two n8 tiles
                uint32_t t0, t1, t2, t3;
                ldsm4(t0, t1, t2, t3, &Bs[buf][(wn * 32 + bt * 16 + rr) * LDS + cc]);
                b[bt * 2 + 0][0] = t0; b[bt * 2 + 0][1] = t2;
                b[bt * 2 + 1][0] = t1; b[bt * 2 + 1][1] = t3;
            }
#pragma unroll
            for (int mt = 0; mt < 4; ++mt)
#pragma unroll
                for (int nt = 0; nt < 4; ++nt)
                    mma16816(c[mt][nt], a[mt][0], a[mt][1], a[mt][2], a[mt][3],
                             b[nt][0], b[nt][1]);
        }
        __syncthreads();
    }

    // ---- epilogue: store C (float2 pairs) ----
    const int rowBase = bm + wm * 64;
    const int colBase = bn + wn * 32;
#pragma unroll
    for (int mt = 0; mt < 4; ++mt) {
#pragma unroll
        for (int nt = 0; nt < 4; ++nt) {
            int row = rowBase + mt * 16 + (lane >> 2);
            int col = colBase + nt * 8 + (lane & 3) * 2;
            float2 v0 = make_float2(c[mt][nt][0], c[mt][nt][1]);
            float2 v1 = make_float2(c[mt][nt][2], c[mt][nt][3]);
            *reinterpret_cast<float2*>(&C[(size_t)row * N + col]) = v0;
            *reinterpret_cast<float2*>(&C[(size_t)(row + 8) * N + col]) = v1;
        }
    }

    if (SUMSQ) {
        // per-thread partial sumsq for the 8 rows it owns (4 m-tiles x 2 halves)
        float acc[4][2];
#pragma unroll
        for (int mt = 0; mt < 4; ++mt) { acc[mt][0] = 0.f; acc[mt][1] = 0.f; }
#pragma unroll
        for (int mt = 0; mt < 4; ++mt)
#pragma unroll
            for (int nt = 0; nt < 4; ++nt) {
                acc[mt][0] += c[mt][nt][0] * c[mt][nt][0] + c[mt][nt][1] * c[mt][nt][1];
                acc[mt][1] += c[mt][nt][2] * c[mt][nt][2] + c[mt][nt][3] * c[mt][nt][3];
            }
        // reduce over the 4 lanes of each quad (they share the same rows)
#pragma unroll
        for (int o = 1; o < 4; o <<= 1)
#pragma unroll
            for (int mt = 0; mt < 4; ++mt) {
                acc[mt][0] += __shfl_xor_sync(0xffffffffu, acc[mt][0], o);
                acc[mt][1] += __shfl_xor_sync(0xffffffffu, acc[mt][1], o);
            }
        if ((lane & 3) == 0) {
            int rq = lane >> 2;
#pragma unroll
            for (int mt = 0; mt < 4; ++mt) {
                red[wn][wm * 64 + mt * 16 + rq]     = acc[mt][0];
                red[wn][wm * 64 + mt * 16 + 8 + rq] = acc[mt][1];
            }
        }
        __syncthreads();
        if (tid < BM) {  // fixed-order cross-warp sum -> deterministic
            float s = red[0][tid] + red[1][tid] + red[2][tid] + red[3][tid];
            partials[(size_t)(bm + tid) * gridN + blockIdx.x] = s;
        }
    }
}

// ---------------- kernel 2: row norms ----------------
__global__ void rownorm_kernel(const float* __restrict__ partials, float* __restrict__ invnorm,
                               int gridN) {
    int row = blockIdx.x * blockDim.x + threadIdx.x;
    if (row >= MDIM) return;
    float s = 0.f;
    for (int j = 0; j < gridN; j++) s += partials[(size_t)row * gridN + j];
    invnorm[row] = sqrtf((float)NBANK) * rsqrtf(s);
}

// ---------------- kernel 3: G = fp16(gelu(S * invnorm[row])) ----------------
__global__ void gelu_kernel(const float4* __restrict__ S, uint2* __restrict__ G,
                            const float* __restrict__ invnorm, int n4) {
    int i = blockIdx.x * blockDim.x + threadIdx.x;
    if (i >= n4) return;
    float sc = invnorm[i >> 11];  // NBANK/4 = 2048 float4 per row
    float4 x = S[i];
    float a0 = x.x * sc, a1 = x.y * sc, a2 = x.z * sc, a3 = x.w * sc;
    // exact GELU: x * Phi(x) (Phi = standard normal CDF = 0.5*(1+erf(x/sqrt2)))
    float g0 = a0 * normcdff(a0);
    float g1 = a1 * normcdff(a1);
    float g2 = a2 * normcdff(a2);
    float g3 = a3 * normcdff(a3);
    __half2 h0 = __floats2half2_rn(g0, g1);
    __half2 h1 = __floats2half2_rn(g2, g3);
    uint2 o;
    o.x = *reinterpret_cast<unsigned*>(&h0);
    o.y = *reinterpret_cast<unsigned*>(&h1);
    G[i] = o;
}

// ---------------- launch ----------------
extern "C" void kernel_launch(void* const* d_in, const int* in_sizes, int n_in,
                              void* d_out, int out_size) {
    const float* q = (const float*)d_in[0];  // [4,2048,1024]
    const float* k = (const float*)d_in[1];  // [8192,1024]
    const float* v = (const float*)d_in[2];  // [8192,1024]
    float* out = (float*)d_out;              // [4,2048,1024]

    __half *qh, *kh, *vt, *G;
    float *S, *partials, *invn;
    cudaGetSymbolAddress((void**)&qh, g_qh);
    cudaGetSymbolAddress((void**)&kh, g_kh);
    cudaGetSymbolAddress((void**)&vt, g_vhT);
    cudaGetSymbolAddress((void**)&S, g_S);
    cudaGetSymbolAddress((void**)&G, g_G);
    cudaGetSymbolAddress((void**)&partials, g_partials);
    cudaGetSymbolAddress((void**)&invn, g_invnorm);

    // 0) input conversion
    const int QN4 = MDIM * KDIM / 4;   // 2,097,152
    const int KN4 = NBANK * KDIM / 4;  // 2,097,152
    f2h_kernel<<<(QN4 + 255) / 256, 256>>>((const float4*)q, (uint2*)qh, QN4);
    f2h_kernel<<<(KN4 + 255) / 256, 256>>>((const float4*)k, (uint2*)kh, KN4);
    transpose_f2h_kernel<<<dim3(ODIM / 32, NBANK / 32), dim3(32, 8)>>>(v, vt);

    // 1) S = q * k^T (+ per-tile sumsq partials)
    gemm_nt_kernel<true><<<dim3(NBANK / 128, MDIM / 128), 256>>>(
        qh, kh, S, KDIM, NBANK, partials, G1_GRIDN);

    // 2) row inverse norms (deterministic fixed-order sum)
    rownorm_kernel<<<MDIM / 256, 256>>>(partials, invn, G1_GRIDN);

    // 3) G = gelu(S * invnorm) in fp16
    const int SN4 = (int)((size_t)MDIM * NBANK / 4);  // 16,777,216
    gelu_kernel<<<(SN4 + 255) / 256, 256>>>((const float4*)S, (uint2*)G, invn, SN4);

    // 4) out = G * v   (B = vT[o][n], NT form)
    gemm_nt_kernel<false><<<dim3(ODIM / 128, MDIM / 128), 256>>>(
        G, vt, out, NBANK, ODIM, nullptr, 0);
}